// round 5
// baseline (speedup 1.0000x reference)
#include <cuda_runtime.h>
#include <math.h>
#include <stdint.h>

#define N_TOK 32768
#define F_IN  512
#define F_HID 2048
#define F_OUT 512

// ---------------- scratch (static device globals; no runtime alloc) ----------
__device__ float g_lo1[F_IN],  g_cp1[F_IN],  g_rd1[F_IN];
__device__ float g_lo2[F_HID], g_cp2[F_HID], g_rd2[F_HID];
__device__ float g_Y1[F_IN * F_HID];                 // solve(M1^T, W1^T): [512][2048]
__device__ float g_Y2[F_HID * F_OUT];                // [2048][512]
__device__ int8_t g_w1a[F_HID * F_IN];               // W1p hi digit [2048][512]
__device__ int8_t g_w1b[F_HID * F_IN];               // W1p lo digit
__device__ float  g_sw1[F_HID];
__device__ int8_t g_w2a[F_OUT * F_HID];              // W2p digits [512][2048]
__device__ int8_t g_w2b[F_OUT * F_HID];
__device__ float  g_sw2[F_OUT];
__device__ int8_t g_xa[(size_t)N_TOK * F_IN];        // x digits  16 MB each
__device__ int8_t g_xb[(size_t)N_TOK * F_IN];
__device__ float  g_sx[N_TOK];
__device__ float  g_h[(size_t)N_TOK * F_HID];        // h fp32    256 MB
__device__ int8_t g_ha[(size_t)N_TOK * F_HID];       // h digits  64 MB each
__device__ int8_t g_hb[(size_t)N_TOK * F_HID];
__device__ float  g_sh[N_TOK];

// ======================= helpers =======================
__device__ __forceinline__ uint32_t smem_u32(const void* p) {
    uint32_t a;
    asm("{ .reg .u64 t; cvta.to.shared.u64 t, %1; cvt.u32.u64 %0, t; }"
        : "=r"(a) : "l"(p));
    return a;
}
__device__ __forceinline__ void cp16(uint32_t dst, const void* src) {
    asm volatile("cp.async.cg.shared.global [%0], [%1], 16;" :: "r"(dst), "l"(src));
}
__device__ __forceinline__ void cp_commit() {
    asm volatile("cp.async.commit_group;" ::: "memory");
}
template <int NN> __device__ __forceinline__ void cp_wait() {
    asm volatile("cp.async.wait_group %0;" :: "n"(NN) : "memory");
}
__device__ __forceinline__ void ldm_x4(uint32_t& r0, uint32_t& r1, uint32_t& r2,
                                       uint32_t& r3, uint32_t a) {
    asm volatile("ldmatrix.sync.aligned.m8n8.x4.shared.b16 {%0,%1,%2,%3}, [%4];"
        : "=r"(r0), "=r"(r1), "=r"(r2), "=r"(r3) : "r"(a));
}
// s8 MMA m16n8k32, s32 accumulate
__device__ __forceinline__ void mma_s8(int* c, const uint32_t* a,
                                       uint32_t b0, uint32_t b1) {
    asm volatile("mma.sync.aligned.m16n8k32.row.col.s32.s8.s8.s32 "
        "{%0,%1,%2,%3}, {%4,%5,%6,%7}, {%8,%9}, {%0,%1,%2,%3};"
        : "+r"(c[0]), "+r"(c[1]), "+r"(c[2]), "+r"(c[3])
        : "r"(a[0]), "r"(a[1]), "r"(a[2]), "r"(a[3]), "r"(b0), "r"(b1));
}
// quantize v -> 128*hi + lo  (hi in [-127,127], lo in [-64,63]) at scale iq=16256/amax
__device__ __forceinline__ void qpair(float v, float iq, int& hi, int& lo) {
    int a16 = __float2int_rn(v * iq);
    hi = (a16 + 64) >> 7;
    lo = a16 - (hi << 7);
}
__device__ __forceinline__ uint32_t pack4(int a, int b, int c, int d) {
    return (a & 0xFF) | ((b & 0xFF) << 8) | ((c & 0xFF) << 16) | ((d & 0xFF) << 24);
}

// ======================= prep kernels =======================
__global__ void prep_both(const float* d1, const float* l1, const float* u1,
                          const float* d2, const float* l2, const float* u2,
                          float* lo1, float* cp1, float* rd1,
                          float* lo2, float* cp2, float* rd2) {
    __shared__ float sd[2048], slo[2048], sup[2048];
    const float *d, *l, *u; float *lo, *cp, *rd; int n;
    if (blockIdx.x == 0) { d = d1; l = l1; u = u1; lo = lo1; cp = cp1; rd = rd1; n = F_IN; }
    else                 { d = d2; l = l2; u = u2; lo = lo2; cp = cp2; rd = rd2; n = F_HID; }
    int t = threadIdx.x;
    for (int i = t; i < n; i += blockDim.x) {
        float di = d[i];
        float sp = (di > 20.f) ? di : log1pf(expf(di));
        sd[i]  = sp + 2.f;
        slo[i] = (i > 0)     ? tanhf(u[i - 1]) : 0.f;   // sub of M^T
        sup[i] = (i < n - 1) ? tanhf(l[i])     : 0.f;   // super of M^T
    }
    __syncthreads();
    if (t == 0) {
        float cprev = 0.f;
        for (int i = 0; i < n; i++) {
            float den = sd[i] - slo[i] * cprev;
            float r = 1.f / den;
            sd[i] = r;
            cprev = sup[i] * r;
            sup[i] = cprev;
        }
    }
    __syncthreads();
    for (int i = t; i < n; i += blockDim.x) {
        rd[i] = sd[i]; cp[i] = sup[i]; lo[i] = slo[i];
    }
}

__device__ __forceinline__ void solve_one(
    const float* __restrict__ lo, const float* __restrict__ cp,
    const float* __restrict__ rd, const float* __restrict__ r,
    int n, int nrhs, float* __restrict__ Y, int j) {
    float z = r[0] * rd[0];
    Y[j] = z;
#pragma unroll 4
    for (int i = 1; i < n; i++) {
        z = (r[i] - lo[i] * z) * rd[i];
        Y[(size_t)i * nrhs + j] = z;
    }
    float y = z;
#pragma unroll 4
    for (int i = n - 2; i >= 0; i--) {
        y = Y[(size_t)i * nrhs + j] - cp[i] * y;
        Y[(size_t)i * nrhs + j] = y;
    }
}

// blocks 0..15: system 1 (2048 rhs); blocks 16..19: system 2 (512 rhs)
__global__ void solve_both(const float* lo1, const float* cp1, const float* rd1,
                           const float* W1, float* Y1,
                           const float* lo2, const float* cp2, const float* rd2,
                           const float* W2, float* Y2) {
    int bid = blockIdx.x, t = threadIdx.x;
    if (bid < 16) {
        int j = bid * 128 + t;
        solve_one(lo1, cp1, rd1, W1 + (size_t)j * F_IN, F_IN, F_HID, Y1, j);
    } else {
        int j = (bid - 16) * 128 + t;
        solve_one(lo2, cp2, rd2, W2 + (size_t)j * F_HID, F_HID, F_OUT, Y2, j);
    }
}

// blocks 0..2047: W1 rows; 2048..2559: W2 rows; 2560+: x rows (8 rows/block)
__global__ void quant_all(const float* __restrict__ Y1, const float* __restrict__ Y2,
                          const float4* __restrict__ x4,
                          int8_t* w1a, int8_t* w1b, float* sw1,
                          int8_t* w2a, int8_t* w2b, float* sw2,
                          uint32_t* xa, uint32_t* xb, float* sx) {
    int b = blockIdx.x, t = threadIdx.x;
    if (b < 2560) {
        const float* Y; int Kd, nr, n; int8_t *wa, *wb; float* sw;
        if (b < 2048) { Y = Y1; Kd = F_IN;  nr = F_HID; n = b;        wa = w1a; wb = w1b; sw = sw1; }
        else          { Y = Y2; Kd = F_HID; nr = F_OUT; n = b - 2048; wa = w2a; wb = w2b; sw = sw2; }
        float m = 0.f;
        for (int i = t; i < Kd; i += 256) m = fmaxf(m, fabsf(Y[(size_t)i * nr + n]));
        __shared__ float red[8];
        for (int o = 16; o; o >>= 1) m = fmaxf(m, __shfl_xor_sync(~0u, m, o));
        if ((t & 31) == 0) red[t >> 5] = m;
        __syncthreads();
        float amax = red[0];
#pragma unroll
        for (int i = 1; i < 8; i++) amax = fmaxf(amax, red[i]);
        float iq = amax > 0.f ? 16256.f / amax : 0.f;
        if (t == 0) sw[n] = amax > 0.f ? amax / 16256.f : 0.f;
        for (int i = t; i < Kd; i += 256) {
            int hi, lo;
            qpair(Y[(size_t)i * nr + n], iq, hi, lo);
            wa[(size_t)n * Kd + i] = (int8_t)hi;
            wb[(size_t)n * Kd + i] = (int8_t)lo;
        }
    } else {
        int row = (b - 2560) * 8 + (t >> 5);
        int lane = t & 31;
        const float4* xr = x4 + (size_t)row * 128;
        float4 v[4]; float m = 0.f;
#pragma unroll
        for (int w = 0; w < 4; w++) {
            v[w] = xr[lane + 32 * w];
            m = fmaxf(m, fmaxf(fmaxf(fabsf(v[w].x), fabsf(v[w].y)),
                               fmaxf(fabsf(v[w].z), fabsf(v[w].w))));
        }
        for (int o = 16; o; o >>= 1) m = fmaxf(m, __shfl_xor_sync(~0u, m, o));
        float iq = m > 0.f ? 16256.f / m : 0.f;
        if (lane == 0) sx[row] = m > 0.f ? m / 16256.f : 0.f;
#pragma unroll
        for (int w = 0; w < 4; w++) {
            int h0, l0, h1, l1, h2, l2, h3, l3;
            qpair(v[w].x, iq, h0, l0); qpair(v[w].y, iq, h1, l1);
            qpair(v[w].z, iq, h2, l2); qpair(v[w].w, iq, h3, l3);
            xa[(size_t)row * 128 + lane + 32 * w] = pack4(h0, h1, h2, h3);
            xb[(size_t)row * 128 + lane + 32 * w] = pack4(l0, l1, l2, l3);
        }
    }
}

// row-wise requantization of h (fp32 [N_TOK][2048] -> digits + scale)
__global__ void quant_h(const float4* __restrict__ h4, uint32_t* __restrict__ ha,
                        uint32_t* __restrict__ hb, float* __restrict__ sh) {
    int row = blockIdx.x, t = threadIdx.x;
    const float4* hr = h4 + (size_t)row * 512;
    float4 v0 = hr[t], v1 = hr[t + 256];
    float m = fmaxf(fmaxf(fmaxf(fabsf(v0.x), fabsf(v0.y)), fmaxf(fabsf(v0.z), fabsf(v0.w))),
                    fmaxf(fmaxf(fabsf(v1.x), fabsf(v1.y)), fmaxf(fabsf(v1.z), fabsf(v1.w))));
    __shared__ float red[8];
    for (int o = 16; o; o >>= 1) m = fmaxf(m, __shfl_xor_sync(~0u, m, o));
    if ((t & 31) == 0) red[t >> 5] = m;
    __syncthreads();
    float amax = red[0];
#pragma unroll
    for (int i = 1; i < 8; i++) amax = fmaxf(amax, red[i]);
    float iq = amax > 0.f ? 16256.f / amax : 0.f;
    if (t == 0) sh[row] = amax > 0.f ? amax / 16256.f : 0.f;
    int h0, l0, h1, l1, h2, l2, h3, l3;
    qpair(v0.x, iq, h0, l0); qpair(v0.y, iq, h1, l1);
    qpair(v0.z, iq, h2, l2); qpair(v0.w, iq, h3, l3);
    ha[(size_t)row * 512 + t] = pack4(h0, h1, h2, h3);
    hb[(size_t)row * 512 + t] = pack4(l0, l1, l2, l3);
    qpair(v1.x, iq, h0, l0); qpair(v1.y, iq, h1, l1);
    qpair(v1.z, iq, h2, l2); qpair(v1.w, iq, h3, l3);
    ha[(size_t)row * 512 + t + 256] = pack4(h0, h1, h2, h3);
    hb[(size_t)row * 512 + t + 256] = pack4(l0, l1, l2, l3);
}

// ======================= int8 dual-digit GEMM =======================
// C = sa[m]*sb[n]*(16384*S11 + 128*(S10+S01)) + bias  (+relu)
// CTA 128x128, BK=32 int8, 8 warps (32m x 64n warp tile), 4-stage cp.async.
#define GSTAGES 4
#define TILE_B  4096u                   // 128x32 int8
#define STG_BYTES (4u * TILE_B)         // A1,A0,B1,B0 = 16 KB/stage
#define GEMM_SMEM (GSTAGES * STG_BYTES) // 64 KB

// swizzled 16B-seg address in a 128x32 int8 tile (rows packed 4/128B line)
__device__ __forceinline__ uint32_t swz8(int r, int s) {
    int line = r >> 2;
    int slot = (((r & 3) << 1) | s) ^ (line & 1);
    return (uint32_t)(line * 128 + slot * 16);
}

__device__ __forceinline__ void load_stage(uint32_t sbase, int buf,
    const int8_t* A1, const int8_t* A0, const int8_t* B1, const int8_t* B0,
    int rowB, int colB, int K, int off, int tid) {
    uint32_t s0 = sbase + (uint32_t)buf * STG_BYTES;
    int r = tid >> 1, sg = tid & 1;
    uint32_t sw = swz8(r, sg);
    size_t ga = (size_t)(rowB + r) * K + off + sg * 16;
    size_t gb = (size_t)(colB + r) * K + off + sg * 16;
    cp16(s0 + sw,              A1 + ga);
    cp16(s0 + TILE_B + sw,     A0 + ga);
    cp16(s0 + 2 * TILE_B + sw, B1 + gb);
    cp16(s0 + 3 * TILE_B + sw, B0 + gb);
    cp_commit();
}

template <bool RELU>
__global__ void __launch_bounds__(256, 1) gemm_s8(
    const int8_t* __restrict__ A1, const int8_t* __restrict__ A0,
    const float* __restrict__ sA,
    const int8_t* __restrict__ B1, const int8_t* __restrict__ B0,
    const float* __restrict__ sB,
    const float* __restrict__ bias, float* __restrict__ C,
    int N, int K) {
    extern __shared__ char smem[];
    uint32_t sb = smem_u32(smem);
    const int tid = threadIdx.x;
    const int lane = tid & 31, wid = tid >> 5;
    const int wm = wid & 3, wn = wid >> 2;       // warp tile 32(m) x 64(n)
    const int rowB = blockIdx.y * 128, colB = blockIdx.x * 128;
    const int per = K >> 5;

    int acc11[2][8][4] = {};
    int accX [2][8][4] = {};

#pragma unroll
    for (int s = 0; s < GSTAGES - 1; s++)
        load_stage(sb, s, A1, A0, B1, B0, rowB, colB, K, s << 5, tid);

    // ldmatrix lane->address constants
    const int rA = (lane & 7) + ((lane >> 3) & 1) * 8;  // A: tiles m0..7/s0, m8..15/s0, m0..7/s1, m8..15/s1
    const int sA_seg = lane >> 4;
    const int rB = (lane & 7) + (lane >> 4) * 8;        // B: tiles n0..7/s0, n0..7/s1, n8..15/s0, n8..15/s1
    const int sB_seg = (lane >> 3) & 1;

    for (int s = 0; s < per; s++) {
        cp_wait<GSTAGES - 2>();
        __syncthreads();

        int pf = s + GSTAGES - 1;
        if (pf < per)
            load_stage(sb, pf % GSTAGES, A1, A0, B1, B0, rowB, colB, K, pf << 5, tid);
        else
            cp_commit();

        uint32_t base = sb + (uint32_t)(s % GSTAGES) * STG_BYTES;

        uint32_t a1f[2][4], a0f[2][4];
#pragma unroll
        for (int mt = 0; mt < 2; mt++) {
            uint32_t ad = base + swz8(wm * 32 + mt * 16 + rA, sA_seg);
            ldm_x4(a1f[mt][0], a1f[mt][1], a1f[mt][2], a1f[mt][3], ad);
            ldm_x4(a0f[mt][0], a0f[mt][1], a0f[mt][2], a0f[mt][3], ad + TILE_B);
        }
#pragma unroll
        for (int g = 0; g < 4; g++) {
            uint32_t bd = base + 2 * TILE_B + swz8(wn * 64 + g * 16 + rB, sB_seg);
            uint32_t h0, h1, h2, h3, l0, l1, l2, l3;
            ldm_x4(h0, h1, h2, h3, bd);            // B hi digit: (b0,b1) nLo / nHi
            ldm_x4(l0, l1, l2, l3, bd + TILE_B);   // B lo digit
#pragma unroll
            for (int mt = 0; mt < 2; mt++) {
                mma_s8(acc11[mt][2 * g],     a1f[mt], h0, h1);
                mma_s8(accX [mt][2 * g],     a1f[mt], l0, l1);
                mma_s8(accX [mt][2 * g],     a0f[mt], h0, h1);
                mma_s8(acc11[mt][2 * g + 1], a1f[mt], h2, h3);
                mma_s8(accX [mt][2 * g + 1], a1f[mt], l2, l3);
                mma_s8(accX [mt][2 * g + 1], a0f[mt], h2, h3);
            }
        }
        __syncthreads();
    }

    // epilogue
#pragma unroll
    for (int mt = 0; mt < 2; mt++) {
        int r0 = rowB + wm * 32 + mt * 16 + (lane >> 2);
        float sa0 = sA[r0], sa8 = sA[r0 + 8];
#pragma unroll
        for (int n8 = 0; n8 < 8; n8++) {
            int c = colB + wn * 64 + n8 * 8 + 2 * (lane & 3);
            float sb0 = sB[c], sb1 = sB[c + 1];
            float bz0 = bias[c], bz1 = bias[c + 1];
            const int* S = acc11[mt][n8];
            const int* X = accX[mt][n8];
            float v0 = sa0 * sb0 * (16384.f * (float)S[0] + 128.f * (float)X[0]) + bz0;
            float v1 = sa0 * sb1 * (16384.f * (float)S[1] + 128.f * (float)X[1]) + bz1;
            float v2 = sa8 * sb0 * (16384.f * (float)S[2] + 128.f * (float)X[2]) + bz0;
            float v3 = sa8 * sb1 * (16384.f * (float)S[3] + 128.f * (float)X[3]) + bz1;
            if (RELU) {
                v0 = fmaxf(v0, 0.f); v1 = fmaxf(v1, 0.f);
                v2 = fmaxf(v2, 0.f); v3 = fmaxf(v3, 0.f);
            }
            *(float2*)(C + (size_t)r0 * N + c)       = make_float2(v0, v1);
            *(float2*)(C + (size_t)(r0 + 8) * N + c) = make_float2(v2, v3);
        }
    }
}

// ======================= launch =======================
extern "C" void kernel_launch(void* const* d_in, const int* in_sizes, int n_in,
                              void* d_out, int out_size) {
    const float* x  = (const float*)d_in[0];
    const float* d1 = (const float*)d_in[1];
    const float* l1 = (const float*)d_in[2];
    const float* u1 = (const float*)d_in[3];
    const float* W1 = (const float*)d_in[4];
    const float* b1 = (const float*)d_in[5];
    const float* d2 = (const float*)d_in[6];
    const float* l2 = (const float*)d_in[7];
    const float* u2 = (const float*)d_in[8];
    const float* W2 = (const float*)d_in[9];
    const float* b2 = (const float*)d_in[10];
    float* out = (float*)d_out;

    float *lo1, *cp1, *rd1, *lo2, *cp2, *rd2, *Y1, *Y2;
    float *sw1, *sw2, *sx, *sh, *h;
    int8_t *w1a, *w1b, *w2a, *w2b, *xa, *xb, *ha, *hb;
    cudaGetSymbolAddress((void**)&lo1, g_lo1);
    cudaGetSymbolAddress((void**)&cp1, g_cp1);
    cudaGetSymbolAddress((void**)&rd1, g_rd1);
    cudaGetSymbolAddress((void**)&lo2, g_lo2);
    cudaGetSymbolAddress((void**)&cp2, g_cp2);
    cudaGetSymbolAddress((void**)&rd2, g_rd2);
    cudaGetSymbolAddress((void**)&Y1,  g_Y1);
    cudaGetSymbolAddress((void**)&Y2,  g_Y2);
    cudaGetSymbolAddress((void**)&w1a, g_w1a);
    cudaGetSymbolAddress((void**)&w1b, g_w1b);
    cudaGetSymbolAddress((void**)&sw1, g_sw1);
    cudaGetSymbolAddress((void**)&w2a, g_w2a);
    cudaGetSymbolAddress((void**)&w2b, g_w2b);
    cudaGetSymbolAddress((void**)&sw2, g_sw2);
    cudaGetSymbolAddress((void**)&xa,  g_xa);
    cudaGetSymbolAddress((void**)&xb,  g_xb);
    cudaGetSymbolAddress((void**)&sx,  g_sx);
    cudaGetSymbolAddress((void**)&h,   g_h);
    cudaGetSymbolAddress((void**)&ha,  g_ha);
    cudaGetSymbolAddress((void**)&hb,  g_hb);
    cudaGetSymbolAddress((void**)&sh,  g_sh);

    cudaFuncSetAttribute(gemm_s8<true>,
                         cudaFuncAttributeMaxDynamicSharedMemorySize, GEMM_SMEM);
    cudaFuncSetAttribute(gemm_s8<false>,
                         cudaFuncAttributeMaxDynamicSharedMemorySize, GEMM_SMEM);

    // 1) factorize M1^T, M2^T
    prep_both<<<2, 256>>>(d1, l1, u1, d2, l2, u2, lo1, cp1, rd1, lo2, cp2, rd2);
    // 2) fold tridiag solves into weights
    solve_both<<<20, 128>>>(lo1, cp1, rd1, W1, Y1, lo2, cp2, rd2, W2, Y2);
    // 3) quantize weights (transposed read from Y) + x, per-row 14-bit dual digit
    quant_all<<<2560 + N_TOK / 8, 256>>>(Y1, Y2, (const float4*)x,
                                         w1a, w1b, sw1, w2a, w2b, sw2,
                                         (uint32_t*)xa, (uint32_t*)xb, sx);
    // 4) h = relu(x @ W1p^T + b1)  (fp32 out)
    gemm_s8<true><<<dim3(F_HID / 128, N_TOK / 128), 256, GEMM_SMEM>>>(
        xa, xb, sx, w1a, w1b, sw1, b1, h, F_HID, F_IN);
    // 5) requantize h row-wise
    quant_h<<<N_TOK, 256>>>((const float4*)h, (uint32_t*)ha, (uint32_t*)hb, sh);
    // 6) out = h @ W2p^T + b2
    gemm_s8<false><<<dim3(F_OUT / 128, N_TOK / 128), 256, GEMM_SMEM>>>(
        ha, hb, sh, w2a, w2b, sw2, b2, out, F_OUT, F_HID);
}

// round 6
// speedup vs baseline: 2.5887x; 2.5887x over previous
#include <cuda_runtime.h>
#include <cuda_fp16.h>
#include <math.h>
#include <stdint.h>

#define N_TOK 32768
#define F_IN  512
#define F_HID 2048
#define F_OUT 512

// ---------------- scratch (static device globals; no runtime alloc) ----------
__device__ float g_lo1[F_IN],  g_cp1[F_IN],  g_rd1[F_IN];
__device__ float g_lo2[F_HID], g_cp2[F_HID], g_rd2[F_HID];
__device__ float g_Y1[F_IN * F_HID];               // solve(M1^T, W1^T): [512][2048]
__device__ float g_Y2[F_HID * F_OUT];              // [2048][512]
__device__ __half g_W1[F_HID * F_IN];              // folded W1 fp16 [2048][512]
__device__ __half g_W2[F_OUT * F_HID];             // folded W2 fp16 [512][2048]
__device__ __half g_xh[(size_t)N_TOK * F_IN];      // x hi  32 MB
__device__ __half g_xl[(size_t)N_TOK * F_IN];      // x lo
__device__ __half g_hh[(size_t)N_TOK * F_HID];     // h hi  128 MB
__device__ __half g_hl[(size_t)N_TOK * F_HID];     // h lo  128 MB

// ======================= helpers =======================
__device__ __forceinline__ uint32_t smem_u32(const void* p) {
    uint32_t a;
    asm("{ .reg .u64 t; cvta.to.shared.u64 t, %1; cvt.u32.u64 %0, t; }"
        : "=r"(a) : "l"(p));
    return a;
}
__device__ __forceinline__ void cp16(uint32_t dst, const void* src) {
    asm volatile("cp.async.cg.shared.global [%0], [%1], 16;" :: "r"(dst), "l"(src));
}
__device__ __forceinline__ void cp_commit() {
    asm volatile("cp.async.commit_group;" ::: "memory");
}
template <int NN> __device__ __forceinline__ void cp_wait() {
    asm volatile("cp.async.wait_group %0;" :: "n"(NN) : "memory");
}
__device__ __forceinline__ void ldm_x4(uint32_t& r0, uint32_t& r1, uint32_t& r2,
                                       uint32_t& r3, uint32_t a) {
    asm volatile("ldmatrix.sync.aligned.m8n8.x4.shared.b16 {%0,%1,%2,%3}, [%4];"
        : "=r"(r0), "=r"(r1), "=r"(r2), "=r"(r3) : "r"(a));
}
__device__ __forceinline__ void mma_f16(float* c, const uint32_t* a,
                                        uint32_t b0, uint32_t b1) {
    asm volatile("mma.sync.aligned.m16n8k16.row.col.f32.f16.f16.f32 "
        "{%0,%1,%2,%3}, {%4,%5,%6,%7}, {%8,%9}, {%0,%1,%2,%3};"
        : "+f"(c[0]), "+f"(c[1]), "+f"(c[2]), "+f"(c[3])
        : "r"(a[0]), "r"(a[1]), "r"(a[2]), "r"(a[3]), "r"(b0), "r"(b1));
}
__device__ __forceinline__ uint32_t packh(__half a, __half b) {
    return (uint32_t)__half_as_ushort(a) | ((uint32_t)__half_as_ushort(b) << 16);
}
// split fp32 pair -> packed fp16 hi pair + fp16 lo pair
__device__ __forceinline__ void split2h(float a, float b, uint32_t& hi, uint32_t& lo) {
    __half ha = __float2half_rn(a), hb = __float2half_rn(b);
    float ra = a - __half2float(ha), rb = b - __half2float(hb);
    hi = packh(ha, hb);
    lo = packh(__float2half_rn(ra), __float2half_rn(rb));
}

// ======================= prep kernels =======================
__global__ void prep_both(const float* d1, const float* l1, const float* u1,
                          const float* d2, const float* l2, const float* u2,
                          float* lo1, float* cp1, float* rd1,
                          float* lo2, float* cp2, float* rd2) {
    __shared__ float sd[2048], slo[2048], sup[2048];
    const float *d, *l, *u; float *lo, *cp, *rd; int n;
    if (blockIdx.x == 0) { d = d1; l = l1; u = u1; lo = lo1; cp = cp1; rd = rd1; n = F_IN; }
    else                 { d = d2; l = l2; u = u2; lo = lo2; cp = cp2; rd = rd2; n = F_HID; }
    int t = threadIdx.x;
    for (int i = t; i < n; i += blockDim.x) {
        float di = d[i];
        float sp = (di > 20.f) ? di : log1pf(expf(di));
        sd[i]  = sp + 2.f;
        slo[i] = (i > 0)     ? tanhf(u[i - 1]) : 0.f;   // sub of M^T
        sup[i] = (i < n - 1) ? tanhf(l[i])     : 0.f;   // super of M^T
    }
    __syncthreads();
    if (t == 0) {
        float cprev = 0.f;
        for (int i = 0; i < n; i++) {
            float den = sd[i] - slo[i] * cprev;
            float r = 1.f / den;
            sd[i] = r;
            cprev = sup[i] * r;
            sup[i] = cprev;
        }
    }
    __syncthreads();
    for (int i = t; i < n; i += blockDim.x) {
        rd[i] = sd[i]; cp[i] = sup[i]; lo[i] = slo[i];
    }
}

__device__ __forceinline__ void solve_one(
    const float* __restrict__ lo, const float* __restrict__ cp,
    const float* __restrict__ rd, const float* __restrict__ r,
    int n, int nrhs, float* __restrict__ Y, int j) {
    float z = r[0] * rd[0];
    Y[j] = z;
#pragma unroll 4
    for (int i = 1; i < n; i++) {
        z = (r[i] - lo[i] * z) * rd[i];
        Y[(size_t)i * nrhs + j] = z;
    }
    float y = z;
#pragma unroll 4
    for (int i = n - 2; i >= 0; i--) {
        y = Y[(size_t)i * nrhs + j] - cp[i] * y;
        Y[(size_t)i * nrhs + j] = y;
    }
}

__global__ void solve_both(const float* lo1, const float* cp1, const float* rd1,
                           const float* W1, float* Y1,
                           const float* lo2, const float* cp2, const float* rd2,
                           const float* W2, float* Y2) {
    int bid = blockIdx.x, t = threadIdx.x;
    if (bid < 16) {
        int j = bid * 128 + t;
        solve_one(lo1, cp1, rd1, W1 + (size_t)j * F_IN, F_IN, F_HID, Y1, j);
    } else {
        int j = (bid - 16) * 128 + t;
        solve_one(lo2, cp2, rd2, W2 + (size_t)j * F_HID, F_HID, F_OUT, Y2, j);
    }
}

// transpose [R][C] fp32 -> [C][R] fp16
__global__ void trans_f16(const float* __restrict__ in, __half* __restrict__ out,
                          int R, int C) {
    __shared__ float t[32][33];
    int c0 = blockIdx.x * 32, r0 = blockIdx.y * 32;
    int x = threadIdx.x, y = threadIdx.y;
#pragma unroll
    for (int i = 0; i < 32; i += 8)
        t[y + i][x] = in[(size_t)(r0 + y + i) * C + c0 + x];
    __syncthreads();
#pragma unroll
    for (int i = 0; i < 32; i += 8)
        out[(size_t)(c0 + y + i) * R + r0 + x] = __float2half_rn(t[x][y + i]);
}

// split x fp32 -> fp16 hi/lo
__global__ void split_x_f16(const float4* __restrict__ x, uint2* __restrict__ xh,
                            uint2* __restrict__ xl, int n4) {
    int i = blockIdx.x * blockDim.x + threadIdx.x;
    if (i >= n4) return;
    float4 v = x[i];
    uint32_t h0, l0, h1, l1;
    split2h(v.x, v.y, h0, l0);
    split2h(v.z, v.w, h1, l1);
    xh[i] = make_uint2(h0, h1);
    xl[i] = make_uint2(l0, l1);
}

// ======================= fp16 2-term mma.sync GEMM =======================
// C = (Ah + Al) @ B^T (+bias)(+relu/split).  B pre-rounded to fp16.
// CTA 128x128, 8 warps (32m x 64n warp tile), BK=32, 2 stages, 2 CTAs/SM.
#define GSTAGES 2
#define TILE_B  8192u                   // 128x32 fp16
#define STG_BYTES (3u * TILE_B)         // Ah, Al, B = 24 KB/stage
#define GEMM_SMEM (GSTAGES * STG_BYTES) // 48 KB

// swizzled byte offset inside a 128x32 fp16 tile (64B rows, 4x16B segs)
__device__ __forceinline__ uint32_t swz(int r, int sg) {
    return (uint32_t)(r * 64 + ((sg ^ ((r >> 1) & 3)) << 4));
}

__device__ __forceinline__ void load_stage(uint32_t sbase, int buf,
    const __half* Ah, const __half* Al, const __half* B,
    int rowB, int colB, int K, int off, int tid) {
    uint32_t s0 = sbase + (uint32_t)buf * STG_BYTES;
#pragma unroll
    for (int i = 0; i < 2; i++) {
        int flat = tid + i * 256;          // 0..511
        int r = flat >> 2, sg = flat & 3;
        uint32_t sw = swz(r, sg);
        size_t ga = (size_t)(rowB + r) * K + off + sg * 8;
        size_t gb = (size_t)(colB + r) * K + off + sg * 8;
        cp16(s0 + sw,              Ah + ga);
        cp16(s0 + TILE_B + sw,     Al + ga);
        cp16(s0 + 2 * TILE_B + sw, B + gb);
    }
    cp_commit();
}

template <bool FUSE>   // FUSE: relu + write fp16 hi/lo (Ch,Cl); else fp32 Cf
__global__ void __launch_bounds__(256, 2) gemm_f16x2(
    const __half* __restrict__ Ah, const __half* __restrict__ Al,
    const __half* __restrict__ B,
    const float* __restrict__ bias, float* __restrict__ Cf,
    __half* __restrict__ Ch, __half* __restrict__ Cl,
    int N, int K) {
    extern __shared__ char smem[];
    uint32_t sb = smem_u32(smem);
    const int tid = threadIdx.x;
    const int lane = tid & 31, wid = tid >> 5;
    const int wm = wid & 3, wn = wid >> 2;       // warp tile 32(m) x 64(n)
    const int rowB = blockIdx.y * 128, colB = blockIdx.x * 128;
    const int per = K >> 5;

    float acc[2][8][4] = {};

    // prologue: stage 0
    load_stage(sb, 0, Ah, Al, B, rowB, colB, K, 0, tid);

    const int lr = lane & 15, kh = lane >> 4;
    const int lg = lane >> 2, lt = lane & 3;

    for (int s = 0; s < per; s++) {
        cp_wait<0>();
        __syncthreads();

        int pf = s + 1;
        if (pf < per)
            load_stage(sb, pf & 1, Ah, Al, B, rowB, colB, K, pf << 5, tid);

        uint32_t sAh = sb + (uint32_t)(s & 1) * STG_BYTES;
        uint32_t sAl = sAh + TILE_B;
        uint32_t sBs = sAh + 2 * TILE_B;
#pragma unroll
        for (int kk = 0; kk < 2; kk++) {
            uint32_t ah[2][4], al[2][4];
#pragma unroll
            for (int mt = 0; mt < 2; mt++) {
                int r = wm * 32 + mt * 16 + lr;
                uint32_t sw = swz(r, 2 * kk + kh);
                ldm_x4(ah[mt][0], ah[mt][1], ah[mt][2], ah[mt][3], sAh + sw);
                ldm_x4(al[mt][0], al[mt][1], al[mt][2], al[mt][3], sAl + sw);
            }
#pragma unroll
            for (int pt = 0; pt < 4; pt++) {
                int r = wn * 64 + pt * 16 + lr;
                uint32_t sw = swz(r, 2 * kk + kh);
                uint32_t b0, b1, b2, b3;
                ldm_x4(b0, b1, b2, b3, sBs + sw);
#pragma unroll
                for (int mt = 0; mt < 2; mt++) {
                    mma_f16(acc[mt][2 * pt],     ah[mt], b0, b2);
                    mma_f16(acc[mt][2 * pt + 1], ah[mt], b1, b3);
                    mma_f16(acc[mt][2 * pt],     al[mt], b0, b2);
                    mma_f16(acc[mt][2 * pt + 1], al[mt], b1, b3);
                }
            }
        }
        __syncthreads();
    }

    // epilogue
#pragma unroll
    for (int mt = 0; mt < 2; mt++) {
        int r0 = rowB + wm * 32 + mt * 16 + lg;
#pragma unroll
        for (int n8 = 0; n8 < 8; n8++) {
            int c = colB + wn * 64 + n8 * 8 + 2 * lt;
            float b0v = bias[c], b1v = bias[c + 1];
            float v0 = acc[mt][n8][0] + b0v;
            float v1 = acc[mt][n8][1] + b1v;
            float v2 = acc[mt][n8][2] + b0v;
            float v3 = acc[mt][n8][3] + b1v;
            if (FUSE) {
                v0 = fmaxf(v0, 0.f); v1 = fmaxf(v1, 0.f);
                v2 = fmaxf(v2, 0.f); v3 = fmaxf(v3, 0.f);
                uint32_t hi, lo;
                split2h(v0, v1, hi, lo);
                *(uint32_t*)(Ch + (size_t)r0 * N + c) = hi;
                *(uint32_t*)(Cl + (size_t)r0 * N + c) = lo;
                split2h(v2, v3, hi, lo);
                *(uint32_t*)(Ch + (size_t)(r0 + 8) * N + c) = hi;
                *(uint32_t*)(Cl + (size_t)(r0 + 8) * N + c) = lo;
            } else {
                *(float2*)(Cf + (size_t)r0 * N + c)       = make_float2(v0, v1);
                *(float2*)(Cf + (size_t)(r0 + 8) * N + c) = make_float2(v2, v3);
            }
        }
    }
}

// ======================= launch =======================
extern "C" void kernel_launch(void* const* d_in, const int* in_sizes, int n_in,
                              void* d_out, int out_size) {
    const float* x  = (const float*)d_in[0];
    const float* d1 = (const float*)d_in[1];
    const float* l1 = (const float*)d_in[2];
    const float* u1 = (const float*)d_in[3];
    const float* W1 = (const float*)d_in[4];
    const float* b1 = (const float*)d_in[5];
    const float* d2 = (const float*)d_in[6];
    const float* l2 = (const float*)d_in[7];
    const float* u2 = (const float*)d_in[8];
    const float* W2 = (const float*)d_in[9];
    const float* b2 = (const float*)d_in[10];
    float* out = (float*)d_out;

    float *lo1, *cp1, *rd1, *lo2, *cp2, *rd2, *Y1, *Y2;
    __half *W1f, *W2f, *xh, *xl, *hh, *hl;
    cudaGetSymbolAddress((void**)&lo1, g_lo1);
    cudaGetSymbolAddress((void**)&cp1, g_cp1);
    cudaGetSymbolAddress((void**)&rd1, g_rd1);
    cudaGetSymbolAddress((void**)&lo2, g_lo2);
    cudaGetSymbolAddress((void**)&cp2, g_cp2);
    cudaGetSymbolAddress((void**)&rd2, g_rd2);
    cudaGetSymbolAddress((void**)&Y1,  g_Y1);
    cudaGetSymbolAddress((void**)&Y2,  g_Y2);
    cudaGetSymbolAddress((void**)&W1f, g_W1);
    cudaGetSymbolAddress((void**)&W2f, g_W2);
    cudaGetSymbolAddress((void**)&xh,  g_xh);
    cudaGetSymbolAddress((void**)&xl,  g_xl);
    cudaGetSymbolAddress((void**)&hh,  g_hh);
    cudaGetSymbolAddress((void**)&hl,  g_hl);

    cudaFuncSetAttribute(gemm_f16x2<true>,
                         cudaFuncAttributeMaxDynamicSharedMemorySize, GEMM_SMEM);
    cudaFuncSetAttribute(gemm_f16x2<false>,
                         cudaFuncAttributeMaxDynamicSharedMemorySize, GEMM_SMEM);

    // 1) factorize M1^T, M2^T
    prep_both<<<2, 256>>>(d1, l1, u1, d2, l2, u2, lo1, cp1, rd1, lo2, cp2, rd2);
    // 2) fold tridiag solves into weights: Y = solve(M^T, W^T)
    solve_both<<<20, 128>>>(lo1, cp1, rd1, W1, Y1, lo2, cp2, rd2, W2, Y2);
    // 3) transpose folded weights to row-major fp16
    trans_f16<<<dim3(F_HID / 32, F_IN / 32),  dim3(32, 8)>>>(Y1, W1f, F_IN,  F_HID);
    trans_f16<<<dim3(F_OUT / 32, F_HID / 32), dim3(32, 8)>>>(Y2, W2f, F_HID, F_OUT);
    // 4) split x into fp16 hi/lo (exact to 2^-24)
    {
        int n4 = (N_TOK * F_IN) / 4;
        split_x_f16<<<(n4 + 255) / 256, 256>>>((const float4*)x, (uint2*)xh, (uint2*)xl, n4);
    }
    // 5) h = relu(x @ W1p^T + b1), stored as fp16 hi/lo
    gemm_f16x2<true><<<dim3(F_HID / 128, N_TOK / 128), 256, GEMM_SMEM>>>(
        xh, xl, W1f, b1, nullptr, hh, hl, F_HID, F_IN);
    // 6) out = h @ W2p^T + b2 (fp32)
    gemm_f16x2<false><<<dim3(F_OUT / 128, N_TOK / 128), 256, GEMM_SMEM>>>(
        hh, hl, W2f, b2, out, nullptr, nullptr, F_OUT, F_HID);
}

// round 7
// speedup vs baseline: 3.4794x; 1.3441x over previous
#include <cuda_runtime.h>
#include <cuda_fp16.h>
#include <math.h>
#include <stdint.h>

#define N_TOK 32768
#define F_IN  512
#define F_HID 2048
#define F_OUT 512

// ---------------- scratch (static device globals; no runtime alloc) ----------
__device__ float g_lo1[F_IN],  g_cp1[F_IN],  g_rd1[F_IN];
__device__ float g_lo2[F_HID], g_cp2[F_HID], g_rd2[F_HID];
__device__ float g_Y1[F_IN * F_HID];               // solve(M1^T, W1^T): [512][2048]
__device__ float g_Y2[F_HID * F_OUT];              // [2048][512]
__device__ __half g_W1[F_HID * F_IN];              // folded W1 fp16 [2048][512]
__device__ __half g_W2[F_OUT * F_HID];             // folded W2 fp16 [512][2048]
__device__ __half g_x16[(size_t)N_TOK * F_IN];     // x fp16   32 MB
__device__ __half g_h16[(size_t)N_TOK * F_HID];    // h fp16  128 MB

// ======================= helpers =======================
__device__ __forceinline__ uint32_t smem_u32(const void* p) {
    uint32_t a;
    asm("{ .reg .u64 t; cvta.to.shared.u64 t, %1; cvt.u32.u64 %0, t; }"
        : "=r"(a) : "l"(p));
    return a;
}
__device__ __forceinline__ void cp16(uint32_t dst, const void* src) {
    asm volatile("cp.async.cg.shared.global [%0], [%1], 16;" :: "r"(dst), "l"(src));
}
__device__ __forceinline__ void cp_commit() {
    asm volatile("cp.async.commit_group;" ::: "memory");
}
template <int NN> __device__ __forceinline__ void cp_wait() {
    asm volatile("cp.async.wait_group %0;" :: "n"(NN) : "memory");
}
__device__ __forceinline__ void ldm_x4(uint32_t& r0, uint32_t& r1, uint32_t& r2,
                                       uint32_t& r3, uint32_t a) {
    asm volatile("ldmatrix.sync.aligned.m8n8.x4.shared.b16 {%0,%1,%2,%3}, [%4];"
        : "=r"(r0), "=r"(r1), "=r"(r2), "=r"(r3) : "r"(a));
}
__device__ __forceinline__ void mma_f16(float* c, const uint32_t* a,
                                        uint32_t b0, uint32_t b1) {
    asm volatile("mma.sync.aligned.m16n8k16.row.col.f32.f16.f16.f32 "
        "{%0,%1,%2,%3}, {%4,%5,%6,%7}, {%8,%9}, {%0,%1,%2,%3};"
        : "+f"(c[0]), "+f"(c[1]), "+f"(c[2]), "+f"(c[3])
        : "r"(a[0]), "r"(a[1]), "r"(a[2]), "r"(a[3]), "r"(b0), "r"(b1));
}
__device__ __forceinline__ uint32_t packh(__half a, __half b) {
    return (uint32_t)__half_as_ushort(a) | ((uint32_t)__half_as_ushort(b) << 16);
}

// ======================= prep kernels =======================
__global__ void prep_both(const float* d1, const float* l1, const float* u1,
                          const float* d2, const float* l2, const float* u2,
                          float* lo1, float* cp1, float* rd1,
                          float* lo2, float* cp2, float* rd2) {
    __shared__ float sd[2048], slo[2048], sup[2048];
    const float *d, *l, *u; float *lo, *cp, *rd; int n;
    if (blockIdx.x == 0) { d = d1; l = l1; u = u1; lo = lo1; cp = cp1; rd = rd1; n = F_IN; }
    else                 { d = d2; l = l2; u = u2; lo = lo2; cp = cp2; rd = rd2; n = F_HID; }
    int t = threadIdx.x;
    for (int i = t; i < n; i += blockDim.x) {
        float di = d[i];
        float sp = (di > 20.f) ? di : log1pf(expf(di));
        sd[i]  = sp + 2.f;
        slo[i] = (i > 0)     ? tanhf(u[i - 1]) : 0.f;   // sub of M^T
        sup[i] = (i < n - 1) ? tanhf(l[i])     : 0.f;   // super of M^T
    }
    __syncthreads();
    if (t == 0) {
        float cprev = 0.f;
        for (int i = 0; i < n; i++) {
            float den = sd[i] - slo[i] * cprev;
            float r = 1.f / den;
            sd[i] = r;
            cprev = sup[i] * r;
            sup[i] = cprev;
        }
    }
    __syncthreads();
    for (int i = t; i < n; i += blockDim.x) {
        rd[i] = sd[i]; cp[i] = sup[i]; lo[i] = slo[i];
    }
}

__device__ __forceinline__ void solve_one(
    const float* __restrict__ lo, const float* __restrict__ cp,
    const float* __restrict__ rd, const float* __restrict__ r,
    int n, int nrhs, float* __restrict__ Y, int j) {
    float z = r[0] * rd[0];
    Y[j] = z;
#pragma unroll 4
    for (int i = 1; i < n; i++) {
        z = (r[i] - lo[i] * z) * rd[i];
        Y[(size_t)i * nrhs + j] = z;
    }
    float y = z;
#pragma unroll 4
    for (int i = n - 2; i >= 0; i--) {
        y = Y[(size_t)i * nrhs + j] - cp[i] * y;
        Y[(size_t)i * nrhs + j] = y;
    }
}

__global__ void solve_both(const float* lo1, const float* cp1, const float* rd1,
                           const float* W1, float* Y1,
                           const float* lo2, const float* cp2, const float* rd2,
                           const float* W2, float* Y2) {
    int bid = blockIdx.x, t = threadIdx.x;
    if (bid < 16) {
        int j = bid * 128 + t;
        solve_one(lo1, cp1, rd1, W1 + (size_t)j * F_IN, F_IN, F_HID, Y1, j);
    } else {
        int j = (bid - 16) * 128 + t;
        solve_one(lo2, cp2, rd2, W2 + (size_t)j * F_HID, F_HID, F_OUT, Y2, j);
    }
}

// transpose [R][C] fp32 -> [C][R] fp16
__global__ void trans_f16(const float* __restrict__ in, __half* __restrict__ out,
                          int R, int C) {
    __shared__ float t[32][33];
    int c0 = blockIdx.x * 32, r0 = blockIdx.y * 32;
    int x = threadIdx.x, y = threadIdx.y;
#pragma unroll
    for (int i = 0; i < 32; i += 8)
        t[y + i][x] = in[(size_t)(r0 + y + i) * C + c0 + x];
    __syncthreads();
#pragma unroll
    for (int i = 0; i < 32; i += 8)
        out[(size_t)(c0 + y + i) * R + r0 + x] = __float2half_rn(t[x][y + i]);
}

// cast x fp32 -> fp16
__global__ void cast_f16(const float4* __restrict__ x, uint2* __restrict__ o, int n4) {
    int i = blockIdx.x * blockDim.x + threadIdx.x;
    if (i >= n4) return;
    float4 v = x[i];
    o[i] = make_uint2(packh(__float2half_rn(v.x), __float2half_rn(v.y)),
                      packh(__float2half_rn(v.z), __float2half_rn(v.w)));
}

// ======================= fp16 mma.sync GEMM =======================
// C[M,N] = A[M,K] @ B[N,K]^T (+bias)(+relu).  All fp16 in, fp32 accum.
// CTA 128x128, 8 warps (32m x 64n warp tile), BK=32, 4 stages, 2 CTAs/SM.
#define GSTAGES 4
#define TILE_B  8192u                   // 128x32 fp16
#define STG_BYTES (2u * TILE_B)         // A, B = 16 KB/stage
#define GEMM_SMEM (GSTAGES * STG_BYTES) // 64 KB

// swizzled byte offset inside a 128x32 fp16 tile (64B rows, 4x16B segs)
__device__ __forceinline__ uint32_t swz(int r, int sg) {
    return (uint32_t)(r * 64 + ((sg ^ ((r >> 1) & 3)) << 4));
}

__device__ __forceinline__ void load_stage(uint32_t sbase, int buf,
    const __half* A, const __half* B,
    int rowB, int colB, int K, int off, int tid) {
    uint32_t s0 = sbase + (uint32_t)buf * STG_BYTES;
#pragma unroll
    for (int i = 0; i < 2; i++) {
        int flat = tid + i * 256;          // 0..511
        int r = flat >> 2, sg = flat & 3;
        uint32_t sw = swz(r, sg);
        cp16(s0 + sw,          A + (size_t)(rowB + r) * K + off + sg * 8);
        cp16(s0 + TILE_B + sw, B + (size_t)(colB + r) * K + off + sg * 8);
    }
    cp_commit();
}

template <bool FUSE>   // FUSE: relu + fp16 out (Ch); else bias + fp32 out (Cf)
__global__ void __launch_bounds__(256, 2) gemm_f16(
    const __half* __restrict__ A, const __half* __restrict__ B,
    const float* __restrict__ bias, float* __restrict__ Cf,
    __half* __restrict__ Ch, int N, int K) {
    extern __shared__ char smem[];
    uint32_t sb = smem_u32(smem);
    const int tid = threadIdx.x;
    const int lane = tid & 31, wid = tid >> 5;
    const int wm = wid & 3, wn = wid >> 2;       // warp tile 32(m) x 64(n)
    const int rowB = blockIdx.y * 128, colB = blockIdx.x * 128;
    const int per = K >> 5;

    float acc[2][8][4] = {};

#pragma unroll
    for (int s = 0; s < GSTAGES - 1; s++)
        load_stage(sb, s, A, B, rowB, colB, K, s << 5, tid);

    const int lr = lane & 15, kh = lane >> 4;
    const int lg = lane >> 2, lt = lane & 3;

    for (int s = 0; s < per; s++) {
        cp_wait<GSTAGES - 2>();
        __syncthreads();

        int pf = s + GSTAGES - 1;
        if (pf < per)
            load_stage(sb, pf % GSTAGES, A, B, rowB, colB, K, pf << 5, tid);
        else
            cp_commit();

        uint32_t sA = sb + (uint32_t)(s % GSTAGES) * STG_BYTES;
        uint32_t sBs = sA + TILE_B;
#pragma unroll
        for (int kk = 0; kk < 2; kk++) {
            uint32_t a[2][4];
#pragma unroll
            for (int mt = 0; mt < 2; mt++) {
                int r = wm * 32 + mt * 16 + lr;
                ldm_x4(a[mt][0], a[mt][1], a[mt][2], a[mt][3],
                       sA + swz(r, 2 * kk + kh));
            }
#pragma unroll
            for (int pt = 0; pt < 4; pt++) {
                int r = wn * 64 + pt * 16 + lr;
                uint32_t b0, b1, b2, b3;
                ldm_x4(b0, b1, b2, b3, sBs + swz(r, 2 * kk + kh));
#pragma unroll
                for (int mt = 0; mt < 2; mt++) {
                    mma_f16(acc[mt][2 * pt],     a[mt], b0, b2);
                    mma_f16(acc[mt][2 * pt + 1], a[mt], b1, b3);
                }
            }
        }
        __syncthreads();
    }

    // epilogue
#pragma unroll
    for (int mt = 0; mt < 2; mt++) {
        int r0 = rowB + wm * 32 + mt * 16 + lg;
#pragma unroll
        for (int n8 = 0; n8 < 8; n8++) {
            int c = colB + wn * 64 + n8 * 8 + 2 * lt;
            float b0v = bias[c], b1v = bias[c + 1];
            float v0 = acc[mt][n8][0] + b0v;
            float v1 = acc[mt][n8][1] + b1v;
            float v2 = acc[mt][n8][2] + b0v;
            float v3 = acc[mt][n8][3] + b1v;
            if (FUSE) {
                v0 = fmaxf(v0, 0.f); v1 = fmaxf(v1, 0.f);
                v2 = fmaxf(v2, 0.f); v3 = fmaxf(v3, 0.f);
                *(uint32_t*)(Ch + (size_t)r0 * N + c) =
                    packh(__float2half_rn(v0), __float2half_rn(v1));
                *(uint32_t*)(Ch + (size_t)(r0 + 8) * N + c) =
                    packh(__float2half_rn(v2), __float2half_rn(v3));
            } else {
                *(float2*)(Cf + (size_t)r0 * N + c)       = make_float2(v0, v1);
                *(float2*)(Cf + (size_t)(r0 + 8) * N + c) = make_float2(v2, v3);
            }
        }
    }
}

// ======================= launch =======================
extern "C" void kernel_launch(void* const* d_in, const int* in_sizes, int n_in,
                              void* d_out, int out_size) {
    const float* x  = (const float*)d_in[0];
    const float* d1 = (const float*)d_in[1];
    const float* l1 = (const float*)d_in[2];
    const float* u1 = (const float*)d_in[3];
    const float* W1 = (const float*)d_in[4];
    const float* b1 = (const float*)d_in[5];
    const float* d2 = (const float*)d_in[6];
    const float* l2 = (const float*)d_in[7];
    const float* u2 = (const float*)d_in[8];
    const float* W2 = (const float*)d_in[9];
    const float* b2 = (const float*)d_in[10];
    float* out = (float*)d_out;

    float *lo1, *cp1, *rd1, *lo2, *cp2, *rd2, *Y1, *Y2;
    __half *W1f, *W2f, *x16, *h16;
    cudaGetSymbolAddress((void**)&lo1, g_lo1);
    cudaGetSymbolAddress((void**)&cp1, g_cp1);
    cudaGetSymbolAddress((void**)&rd1, g_rd1);
    cudaGetSymbolAddress((void**)&lo2, g_lo2);
    cudaGetSymbolAddress((void**)&cp2, g_cp2);
    cudaGetSymbolAddress((void**)&rd2, g_rd2);
    cudaGetSymbolAddress((void**)&Y1,  g_Y1);
    cudaGetSymbolAddress((void**)&Y2,  g_Y2);
    cudaGetSymbolAddress((void**)&W1f, g_W1);
    cudaGetSymbolAddress((void**)&W2f, g_W2);
    cudaGetSymbolAddress((void**)&x16, g_x16);
    cudaGetSymbolAddress((void**)&h16, g_h16);

    cudaFuncSetAttribute(gemm_f16<true>,
                         cudaFuncAttributeMaxDynamicSharedMemorySize, GEMM_SMEM);
    cudaFuncSetAttribute(gemm_f16<false>,
                         cudaFuncAttributeMaxDynamicSharedMemorySize, GEMM_SMEM);

    // 1) factorize M1^T, M2^T
    prep_both<<<2, 256>>>(d1, l1, u1, d2, l2, u2, lo1, cp1, rd1, lo2, cp2, rd2);
    // 2) fold tridiag solves into weights: Y = solve(M^T, W^T)
    solve_both<<<20, 128>>>(lo1, cp1, rd1, W1, Y1, lo2, cp2, rd2, W2, Y2);
    // 3) transpose folded weights to row-major fp16
    trans_f16<<<dim3(F_HID / 32, F_IN / 32),  dim3(32, 8)>>>(Y1, W1f, F_IN,  F_HID);
    trans_f16<<<dim3(F_OUT / 32, F_HID / 32), dim3(32, 8)>>>(Y2, W2f, F_HID, F_OUT);
    // 4) cast x to fp16
    {
        int n4 = (N_TOK * F_IN) / 4;
        cast_f16<<<(n4 + 255) / 256, 256>>>((const float4*)x, (uint2*)x16, n4);
    }
    // 5) h = relu(x @ W1p^T + b1) -> fp16
    gemm_f16<true><<<dim3(F_HID / 128, N_TOK / 128), 256, GEMM_SMEM>>>(
        x16, W1f, b1, nullptr, h16, F_HID, F_IN);
    // 6) out = h @ W2p^T + b2 -> fp32
    gemm_f16<false><<<dim3(F_OUT / 128, N_TOK / 128), 256, GEMM_SMEM>>>(
        h16, W2f, b2, out, nullptr, F_OUT, F_HID);
}